// round 1
// baseline (speedup 1.0000x reference)
#include <cuda_runtime.h>
#include <cuda_bf16.h>
#include <math.h>

#define NB   4096
#define TT   16
#define HID  256
#define WHAT 50
#define WHERE 3
#define GG   20
#define IMH  50
#define IMW  50

// ---------------- scratch (device globals; allocation-free) ----------------
__device__ float g_h_rela[NB * HID];
__device__ float g_c_rela[NB * HID];
__device__ float g_zw_prev[2][NB * WHERE];
__device__ float g_zwt_prev[2][NB * WHAT];
__device__ float g_zwb[NB * WHERE];
__device__ float g_glimpse[NB * 400];
__device__ float g_h1[NB * 200];
__device__ float g_enc[NB * 100];
__device__ float g_rel_in[NB * 462];
__device__ float g_tem_in[NB * 615];
__device__ float g_lwhat_in[NB * 562];
__device__ float g_gates[NB * 1024];
__device__ float g_mt[NB * 100];
__device__ float g_msw_where[NB * 6];    // m0..2 | s0..2
__device__ float g_msw_what[NB * 100];   // m0..49 | s0..49

// ---------------- helpers ----------------
__device__ __forceinline__ float sigmoidf_(float x) { return 1.f / (1.f + expf(-x)); }
__device__ __forceinline__ float softplusf_(float x) {
    return x > 0.f ? x + log1pf(expf(-x)) : log1pf(expf(x));
}
__device__ __forceinline__ float warp_sum(float v) {
    #pragma unroll
    for (int o = 16; o > 0; o >>= 1) v += __shfl_xor_sync(0xffffffffu, v, o);
    return v;
}

// ---------------- init ----------------
__global__ void k_init(float* kw, float* kwh) {
    int i = blockIdx.x * blockDim.x + threadIdx.x;
    if (i < NB * HID) { g_h_rela[i] = 0.f; g_c_rela[i] = 0.f; }
    if (i < NB * WHERE) g_zw_prev[0][i] = 0.f;
    if (i < NB * WHAT)  g_zwt_prev[0][i] = 0.f;
    if (i < NB) { kw[i] = 0.f; kwh[i] = 0.f; }
}

// ---------------- z_where_bias = relu(hid @ Wp^T + b) + zwr_l ----------------
__global__ void k_zwb(const float* __restrict__ hid_lt, const float* __restrict__ w,
                      const float* __restrict__ b, const float* __restrict__ zwhere_lt, int t) {
    int gw = (blockIdx.x * blockDim.x + threadIdx.x) >> 5;
    int lane = threadIdx.x & 31;
    if (gw >= NB) return;
    const float* h = hid_lt + (size_t)gw * TT * HID + (size_t)t * HID;
    #pragma unroll
    for (int j = 0; j < 3; j++) {
        float s = 0.f;
        for (int k = lane; k < HID; k += 32) s += h[k] * w[j * HID + k];
        s = warp_sum(s);
        if (lane == 0) {
            g_zwb[gw * 3 + j] = fmaxf(s + b[j], 0.f) +
                                zwhere_lt[(size_t)gw * TT * 3 + (size_t)t * 3 + j];
        }
    }
}

// ---------------- glimpse bilinear sampling ----------------
__device__ __forceinline__ float samp_im(const float* __restrict__ im, int i, int y, int x) {
    if (x < 0 || x >= IMW || y < 0 || y >= IMH) return 0.f;
    return im[(size_t)i * (IMH * IMW) + y * IMW + x];
}

__global__ void k_glimpse(const float* __restrict__ im, const float* __restrict__ zw,
                          float* __restrict__ g) {
    int idx = blockIdx.x * blockDim.x + threadIdx.x;
    if (idx >= NB * 400) return;
    int i = idx / 400, p = idx % 400;
    int a = p / GG, b = p % GG;
    float s = zw[i * 3 + 0], tx = zw[i * 3 + 1], ty = zw[i * 3 + 2];
    float baseb = (2.f * b + 1.f) / (float)GG - 1.f;
    float basea = (2.f * a + 1.f) / (float)GG - 1.f;
    float x = s * baseb + tx;
    float y = s * basea + ty;
    float ix = ((x + 1.f) * (float)IMW - 1.f) * 0.5f;
    float iy = ((y + 1.f) * (float)IMH - 1.f) * 0.5f;
    float x0f = floorf(ix), y0f = floorf(iy);
    float wx = ix - x0f, wy = iy - y0f;
    int x0 = (int)x0f, y0 = (int)y0f;
    float v = samp_im(im, i, y0,     x0    ) * (1.f - wx) * (1.f - wy)
            + samp_im(im, i, y0,     x0 + 1) * wx         * (1.f - wy)
            + samp_im(im, i, y0 + 1, x0    ) * (1.f - wx) * wy
            + samp_im(im, i, y0 + 1, x0 + 1) * wx         * wy;
    g[idx] = v;
}

// ---------------- generic fp32 GEMM: C[M,N] = A[M,K] @ W[N,K]^T ----------------
#define BM 64
#define BN 64
#define BK 16
__global__ void gemm_nt(const float* __restrict__ A, const float* __restrict__ W,
                        const float* __restrict__ b1, const float* __restrict__ b2,
                        float* __restrict__ C, int M, int Nn, int K,
                        int accum, int relu) {
    __shared__ float As[BK][BM];
    __shared__ float Ws[BK][BN];
    int bm = blockIdx.y * BM;
    int bn = blockIdx.x * BN;
    int tid = threadIdx.x;
    int tx = tid & 15, ty = tid >> 4;
    float acc[4][4] = {};
    int kk = tid & 15;
    int r0 = tid >> 4;
    for (int k0 = 0; k0 < K; k0 += BK) {
        int k = k0 + kk;
        #pragma unroll
        for (int rr = 0; rr < 4; rr++) {
            int m = bm + r0 + rr * 16;
            As[kk][r0 + rr * 16] = (k < K) ? A[(size_t)m * K + k] : 0.f;
        }
        #pragma unroll
        for (int rr = 0; rr < 4; rr++) {
            int nn = bn + r0 + rr * 16;
            Ws[kk][r0 + rr * 16] = (k < K && nn < Nn) ? W[(size_t)nn * K + k] : 0.f;
        }
        __syncthreads();
        #pragma unroll
        for (int kq = 0; kq < BK; kq++) {
            float4 av = *reinterpret_cast<const float4*>(&As[kq][ty * 4]);
            float4 wv = *reinterpret_cast<const float4*>(&Ws[kq][tx * 4]);
            float a_[4] = {av.x, av.y, av.z, av.w};
            float w_[4] = {wv.x, wv.y, wv.z, wv.w};
            #pragma unroll
            for (int i = 0; i < 4; i++)
                #pragma unroll
                for (int j = 0; j < 4; j++)
                    acc[i][j] += a_[i] * w_[j];
        }
        __syncthreads();
    }
    #pragma unroll
    for (int i = 0; i < 4; i++) {
        int m = bm + ty * 4 + i;
        #pragma unroll
        for (int j = 0; j < 4; j++) {
            int nn = bn + tx * 4 + j;
            if (nn < Nn) {
                float v = acc[i][j];
                if (b1) v += b1[nn];
                if (b2) v += b2[nn];
                if (accum) v += C[(size_t)m * Nn + nn];
                if (relu) v = fmaxf(v, 0.f);
                C[(size_t)m * Nn + nn] = v;
            }
        }
    }
}

// ---------------- concat kernels ----------------
__global__ void k_concat_rel(const float* __restrict__ zwhere_lt,
                             const float* __restrict__ zw_prev,
                             const float* __restrict__ zwhat_lt,
                             const float* __restrict__ zwt_prev,
                             const float* __restrict__ hid_lt, int t) {
    int idx = blockIdx.x * blockDim.x + threadIdx.x;
    if (idx >= NB * 462) return;
    int i = idx / 462, j = idx % 462;
    float v;
    if (j < 100)      v = g_enc[i * 100 + j];
    else if (j < 103) v = zwhere_lt[(size_t)i * TT * 3 + (size_t)t * 3 + (j - 100)];
    else if (j < 106) v = zw_prev[i * 3 + (j - 103)];
    else if (j < 156) v = zwhat_lt[(size_t)i * TT * 50 + (size_t)t * 50 + (j - 106)];
    else if (j < 206) v = zwt_prev[i * 50 + (j - 156)];
    else              v = hid_lt[(size_t)i * TT * HID + (size_t)t * HID + (j - 206)];
    g_rel_in[idx] = v;
}

__global__ void k_concat_tem(const float* __restrict__ zw_prev,
                             const float* __restrict__ hid_lt, int t) {
    int idx = blockIdx.x * blockDim.x + threadIdx.x;
    if (idx >= NB * 615) return;
    int i = idx / 615, j = idx % 615;
    float v;
    if (j < 100)      v = g_enc[i * 100 + j];
    else if (j < 103) v = zw_prev[i * 3 + (j - 100)];
    else if (j < 359) v = hid_lt[(size_t)i * TT * HID + (size_t)t * HID + (j - 103)];
    else              v = g_h_rela[i * HID + (j - 359)];
    g_tem_in[idx] = v;
}

__global__ void k_concat_lwhat(const float* __restrict__ zwhat_lt,
                               const float* __restrict__ htemp_out, int t) {
    int idx = blockIdx.x * blockDim.x + threadIdx.x;
    if (idx >= NB * 562) return;
    int i = idx / 562, j = idx % 562;
    float v;
    if (j < 50)       v = zwhat_lt[(size_t)i * TT * 50 + (size_t)t * 50 + j];
    else if (j < 306) v = g_h_rela[i * HID + (j - 50)];
    else              v = htemp_out[(size_t)i * TT * HID + (size_t)t * HID + (j - 306)];
    g_lwhat_in[idx] = v;
}

// ---------------- LSTM elementwise ----------------
__global__ void k_lstm_rel(void) {
    int idx = blockIdx.x * blockDim.x + threadIdx.x;
    if (idx >= NB * HID) return;
    int i = idx >> 8, hh = idx & 255;
    const float* gr = g_gates + (size_t)i * 1024;
    float ig = sigmoidf_(gr[hh]);
    float fg = sigmoidf_(gr[256 + hh]);
    float gg = tanhf(gr[512 + hh]);
    float og = sigmoidf_(gr[768 + hh]);
    float c2 = fg * g_c_rela[idx] + ig * gg;
    g_c_rela[idx] = c2;
    g_h_rela[idx] = og * tanhf(c2);
}

__global__ void k_lstm_tem(float* __restrict__ htemp_out, int t) {
    int idx = blockIdx.x * blockDim.x + threadIdx.x;
    if (idx >= NB * HID) return;
    int i = idx >> 8, hh = idx & 255;
    const float* gr = g_gates + (size_t)i * 1024;
    float ig = sigmoidf_(gr[hh]);
    float fg = sigmoidf_(gr[256 + hh]);
    float gg = tanhf(gr[512 + hh]);
    float og = sigmoidf_(gr[768 + hh]);
    float c2 = fg * g_c_rela[idx] + ig * gg;
    htemp_out[(size_t)i * TT * HID + (size_t)t * HID + hh] = og * tanhf(c2);
}

// ---------------- lwhere: 6-dim projection + reparam ----------------
__global__ void k_lwhere(const float* __restrict__ w, const float* __restrict__ b,
                         const float* __restrict__ zwhere_lt, const float* __restrict__ eps_w,
                         int t, float* __restrict__ zw_cur, float* __restrict__ out_zwhere) {
    int gw = (blockIdx.x * blockDim.x + threadIdx.x) >> 5;
    int lane = threadIdx.x & 31;
    if (gw >= NB) return;
    __shared__ float mw[4][6];
    int lw = threadIdx.x >> 5;
    const float* h = g_h_rela + (size_t)gw * HID;
    const float* zl = zwhere_lt + (size_t)gw * TT * 3 + (size_t)t * 3;
    #pragma unroll
    for (int j = 0; j < 6; j++) {
        float s = 0.f;
        for (int k = lane; k < 259; k += 32) {
            float a = (k < 3) ? zl[k] : h[k - 3];
            s += a * w[j * 259 + k];
        }
        s = warp_sum(s);
        if (lane == 0) mw[lw][j] = s + b[j];
    }
    __syncwarp();
    if (lane < 3) {
        float m = mw[lw][lane];
        float sd = softplusf_(mw[lw][3 + lane]) + 1e-4f;
        float e = eps_w[(size_t)gw * TT * 3 + (size_t)t * 3 + lane];
        float z = m + sd * e;
        zw_cur[gw * 3 + lane] = z;
        out_zwhere[(size_t)gw * TT * 3 + (size_t)t * 3 + lane] = z;
        g_msw_where[gw * 6 + lane] = m;
        g_msw_where[gw * 6 + 3 + lane] = sd;
    }
}

// ---------------- what reparam ----------------
__global__ void k_what_elem(const float* __restrict__ eps_t, int t,
                            float* __restrict__ zwt_cur, float* __restrict__ out_zwhat) {
    int idx = blockIdx.x * blockDim.x + threadIdx.x;
    if (idx >= NB * WHAT) return;
    int i = idx / WHAT, j = idx % WHAT;
    float m = g_mt[i * 100 + j];
    float sd = softplusf_(g_mt[i * 100 + 50 + j]) + 1e-4f;
    float z = m + sd * eps_t[(size_t)i * TT * 50 + (size_t)t * 50 + j];
    zwt_cur[i * 50 + j] = z;
    out_zwhat[(size_t)i * TT * 50 + (size_t)t * 50 + j] = z;
    g_msw_what[i * 100 + j] = m;
    g_msw_what[i * 100 + 50 + j] = sd;
}

// ---------------- pres + KL accumulation ----------------
__global__ void k_pres_kl(const float* __restrict__ wp, const float* __restrict__ bp,
                          const float* __restrict__ zwt_cur, const float* __restrict__ zw_cur,
                          const float* __restrict__ htemp_out,
                          const float* __restrict__ u_pres, const float* __restrict__ zpres_lt,
                          int t, float* __restrict__ out_zpres,
                          float* __restrict__ out_klwhat, float* __restrict__ out_klwhere) {
    int gw = (blockIdx.x * blockDim.x + threadIdx.x) >> 5;
    int lane = threadIdx.x & 31;
    if (gw >= NB) return;
    const float* ht = htemp_out + (size_t)gw * TT * HID + (size_t)t * HID;
    const float* hr = g_h_rela + (size_t)gw * HID;
    float s = 0.f;
    for (int k = lane; k < 565; k += 32) {
        float a;
        if (k < 50)       a = zwt_cur[gw * 50 + k];
        else if (k < 53)  a = zw_cur[gw * 3 + (k - 50)];
        else if (k < 309) a = hr[k - 53];
        else              a = ht[k - 309];
        s += a * wp[k];
    }
    s = warp_sum(s);
    float p = sigmoidf_(s + bp[0]);
    float up = u_pres[(size_t)gw * TT + t];
    float zpl = zpres_lt[(size_t)gw * TT + t];
    float zp = (up < p * zpl) ? 1.f : 0.f;
    if (lane == 0) out_zpres[(size_t)gw * TT + t] = zp;

    float kw = 0.f;
    for (int j = lane; j < 50; j += 32) {
        float m = g_msw_what[gw * 100 + j];
        float sd = g_msw_what[gw * 100 + 50 + j];
        kw += -logf(sd) + (sd * sd + m * m) * 0.5f - 0.5f;
    }
    kw = warp_sum(kw);

    float kh = 0.f;
    if (lane < 3) {
        float m = g_msw_where[gw * 6 + lane];
        float sd = g_msw_where[gw * 6 + 3 + lane];
        float m0 = (lane == 0) ? 0.3f : 0.f;
        float s0 = (lane == 0) ? 0.1f : 1.f;
        kh = logf(s0 / sd) + (sd * sd + (m - m0) * (m - m0)) / (2.f * s0 * s0) - 0.5f;
    }
    kh = warp_sum(kh);

    if (lane == 0) {
        out_klwhat[gw]  += kw * zp;
        out_klwhere[gw] += kh * zp;
    }
}

// ---------------- host ----------------
static inline int cdiv(int a, int b) { return (a + b - 1) / b; }

extern "C" void kernel_launch(void* const* d_in, const int* in_sizes, int n_in,
                              void* d_out, int out_size) {
    const float* img       = (const float*)d_in[0];
    const float* zwhat_lt  = (const float*)d_in[1];
    const float* zwhere_lt = (const float*)d_in[2];
    const float* zpres_lt  = (const float*)d_in[3];
    const float* hid_lt    = (const float*)d_in[4];
    const float* eps_where = (const float*)d_in[5];
    const float* eps_what  = (const float*)d_in[6];
    const float* u_pres    = (const float*)d_in[7];
    const float* w_pro     = (const float*)d_in[8];
    const float* b_pro     = (const float*)d_in[9];
    const float* w_ge1     = (const float*)d_in[10];
    const float* b_ge1     = (const float*)d_in[11];
    const float* w_ge2     = (const float*)d_in[12];
    const float* b_ge2     = (const float*)d_in[13];
    const float* wih_rel   = (const float*)d_in[14];
    const float* whh_rel   = (const float*)d_in[15];
    const float* bih_rel   = (const float*)d_in[16];
    const float* bhh_rel   = (const float*)d_in[17];
    const float* wih_tem   = (const float*)d_in[18];
    const float* whh_tem   = (const float*)d_in[19];
    const float* bih_tem   = (const float*)d_in[20];
    const float* bhh_tem   = (const float*)d_in[21];
    const float* w_lwhere  = (const float*)d_in[22];
    const float* b_lwhere  = (const float*)d_in[23];
    const float* w_lwhat   = (const float*)d_in[24];
    const float* b_lwhat   = (const float*)d_in[25];
    const float* w_lpres   = (const float*)d_in[26];
    const float* b_lpres   = (const float*)d_in[27];

    float* out = (float*)d_out;
    float* out_zwhat   = out;                       // NB*TT*50
    float* out_zwhere  = out + 3276800;             // NB*TT*3
    float* out_zpres   = out + 3473408;             // NB*TT
    float* out_klwhat  = out + 3538944;             // NB
    float* out_klwhere = out + 3543040;             // NB
    float* out_htemp   = out + 3547136;             // NB*TT*256

    // symbol addresses for the generic GEMM
    float *p_glimpse, *p_h1, *p_enc, *p_relin, *p_temin, *p_lwin, *p_gates, *p_mt;
    float *p_hrela, *p_zwb, *p_zwprev0, *p_zwtprev0;
    cudaGetSymbolAddress((void**)&p_glimpse, g_glimpse);
    cudaGetSymbolAddress((void**)&p_h1, g_h1);
    cudaGetSymbolAddress((void**)&p_enc, g_enc);
    cudaGetSymbolAddress((void**)&p_relin, g_rel_in);
    cudaGetSymbolAddress((void**)&p_temin, g_tem_in);
    cudaGetSymbolAddress((void**)&p_lwin, g_lwhat_in);
    cudaGetSymbolAddress((void**)&p_gates, g_gates);
    cudaGetSymbolAddress((void**)&p_mt, g_mt);
    cudaGetSymbolAddress((void**)&p_hrela, g_h_rela);
    cudaGetSymbolAddress((void**)&p_zwb, g_zwb);
    cudaGetSymbolAddress((void**)&p_zwprev0, g_zw_prev);
    cudaGetSymbolAddress((void**)&p_zwtprev0, g_zwt_prev);

    float* zwbuf[2]  = { p_zwprev0,  p_zwprev0  + NB * WHERE };
    float* zwtbuf[2] = { p_zwtprev0, p_zwtprev0 + NB * WHAT  };

    k_init<<<cdiv(NB * HID, 256), 256>>>(out_klwhat, out_klwhere);

    for (int t = 0; t < TT; t++) {
        int pb = t & 1;
        int cb = pb ^ 1;

        // 1) z_where_bias
        k_zwb<<<cdiv(NB * 32, 128), 128>>>(hid_lt, w_pro, b_pro, zwhere_lt, t);

        // 2) glimpse(z_where_bias) -> encoder -> g_enc
        k_glimpse<<<cdiv(NB * 400, 256), 256>>>(img, p_zwb, p_glimpse);
        {
            dim3 g1(cdiv(200, BN), NB / BM);
            gemm_nt<<<g1, 256>>>(p_glimpse, w_ge1, b_ge1, nullptr, p_h1, NB, 200, 400, 0, 1);
            dim3 g2(cdiv(100, BN), NB / BM);
            gemm_nt<<<g2, 256>>>(p_h1, w_ge2, b_ge2, nullptr, p_enc, NB, 100, 200, 0, 0);
        }

        // 3) relational LSTM
        k_concat_rel<<<cdiv(NB * 462, 256), 256>>>(zwhere_lt, zwbuf[pb], zwhat_lt, zwtbuf[pb], hid_lt, t);
        {
            dim3 gg(cdiv(1024, BN), NB / BM);
            gemm_nt<<<gg, 256>>>(p_relin, wih_rel, bih_rel, bhh_rel, p_gates, NB, 1024, 462, 0, 0);
            gemm_nt<<<gg, 256>>>(p_hrela, whh_rel, nullptr, nullptr, p_gates, NB, 1024, 256, 1, 0);
        }
        k_lstm_rel<<<cdiv(NB * HID, 256), 256>>>();

        // 4) z_where posterior + sample
        k_lwhere<<<cdiv(NB * 32, 128), 128>>>(w_lwhere, b_lwhere, zwhere_lt, eps_where, t,
                                              zwbuf[cb], out_zwhere);

        // 5) glimpse(z_where_i) -> encoder -> g_enc
        k_glimpse<<<cdiv(NB * 400, 256), 256>>>(img, zwbuf[cb], p_glimpse);
        {
            dim3 g1(cdiv(200, BN), NB / BM);
            gemm_nt<<<g1, 256>>>(p_glimpse, w_ge1, b_ge1, nullptr, p_h1, NB, 200, 400, 0, 1);
            dim3 g2(cdiv(100, BN), NB / BM);
            gemm_nt<<<g2, 256>>>(p_h1, w_ge2, b_ge2, nullptr, p_enc, NB, 100, 200, 0, 0);
        }

        // 6) temporal LSTM (state in = updated h_rela/c_rela; only h_temp kept)
        k_concat_tem<<<cdiv(NB * 615, 256), 256>>>(zwbuf[pb], hid_lt, t);
        {
            dim3 gg(cdiv(1024, BN), NB / BM);
            gemm_nt<<<gg, 256>>>(p_temin, wih_tem, bih_tem, bhh_tem, p_gates, NB, 1024, 615, 0, 0);
            gemm_nt<<<gg, 256>>>(p_hrela, whh_tem, nullptr, nullptr, p_gates, NB, 1024, 256, 1, 0);
        }
        k_lstm_tem<<<cdiv(NB * HID, 256), 256>>>(out_htemp, t);

        // 7) z_what posterior + sample
        k_concat_lwhat<<<cdiv(NB * 562, 256), 256>>>(zwhat_lt, out_htemp, t);
        {
            dim3 gw(cdiv(100, BN), NB / BM);
            gemm_nt<<<gw, 256>>>(p_lwin, w_lwhat, b_lwhat, nullptr, p_mt, NB, 100, 562, 0, 0);
        }
        k_what_elem<<<cdiv(NB * WHAT, 256), 256>>>(eps_what, t, zwtbuf[cb], out_zwhat);

        // 8) presence + KL accumulation
        k_pres_kl<<<cdiv(NB * 32, 128), 128>>>(w_lpres, b_lpres, zwtbuf[cb], zwbuf[cb],
                                               out_htemp, u_pres, zpres_lt, t,
                                               out_zpres, out_klwhat, out_klwhere);
    }
    (void)in_sizes; (void)n_in; (void)out_size;
}

// round 2
// speedup vs baseline: 3.1533x; 3.1533x over previous
#include <cuda_runtime.h>
#include <cuda_bf16.h>
#include <math.h>

#define NB   4096
#define TT   16
#define HID  256
#define WHAT 50
#define WHERE 3
#define GG   20
#define IMH  50
#define IMW  50

// padded K sizes
#define KREL 720   // 462 + 256, pad 2
#define KTEM 880   // 615 + 256, pad 9
#define KLW  576   // 562, pad 14
#define KH1  208   // 200, pad 8

// ---------------- scratch (device globals; allocation-free) ----------------
__device__ float g_h_rela[NB * HID];
__device__ float g_c_rela[NB * HID];
__device__ float g_zw_prev[2][NB * WHERE];
__device__ float g_zwt_prev[2][NB * WHAT];
__device__ float g_zwb[NB * WHERE];
__device__ float g_glimpse[NB * 400];
__device__ float g_h1[NB * KH1];
__device__ float g_enc[NB * 100];
__device__ float g_rel_comb[NB * KREL];
__device__ float g_tem_comb[NB * KTEM];
__device__ float g_lwhat_in[NB * KLW];
__device__ float g_gates[NB * 1024];
__device__ float g_mt[NB * 100];
__device__ float g_msw_where[NB * 6];
__device__ float g_msw_what[NB * 100];
// combined / padded weights
__device__ float g_Wrel[1024 * KREL];
__device__ float g_Wtem[1024 * KTEM];
__device__ float g_brel[1024];
__device__ float g_btem[1024];
__device__ float g_wge2p[100 * KH1];
__device__ float g_wlwhatp[100 * KLW];

// ---------------- helpers ----------------
__device__ __forceinline__ float sigmoidf_(float x) { return 1.f / (1.f + expf(-x)); }
__device__ __forceinline__ float softplusf_(float x) {
    return x > 0.f ? x + log1pf(expf(-x)) : log1pf(expf(x));
}
__device__ __forceinline__ float warp_sum(float v) {
    #pragma unroll
    for (int o = 16; o > 0; o >>= 1) v += __shfl_xor_sync(0xffffffffu, v, o);
    return v;
}

// ---------------- init ----------------
__global__ void k_init(float* kw, float* kwh) {
    int i = blockIdx.x * blockDim.x + threadIdx.x;
    if (i < NB * HID) { g_h_rela[i] = 0.f; g_c_rela[i] = 0.f; }
    if (i < NB * WHERE) g_zw_prev[0][i] = 0.f;
    if (i < NB * WHAT)  g_zwt_prev[0][i] = 0.f;
    if (i < NB) { kw[i] = 0.f; kwh[i] = 0.f; }
}

__global__ void k_zero_pads(void) {
    int i = blockIdx.x * blockDim.x + threadIdx.x;
    if (i >= NB) return;
    for (int j = 718; j < KREL; j++) g_rel_comb[i * KREL + j] = 0.f;
    for (int j = 871; j < KTEM; j++) g_tem_comb[i * KTEM + j] = 0.f;
    for (int j = 562; j < KLW; j++)  g_lwhat_in[i * KLW + j] = 0.f;
    for (int j = 200; j < KH1; j++)  g_h1[i * KH1 + j] = 0.f;
}

// ---------------- weight prep ----------------
__global__ void k_prep_w(const float* __restrict__ w1, int k1,
                         const float* __restrict__ w2, int k2,
                         float* __restrict__ wc, int kc, int nrows) {
    int idx = blockIdx.x * blockDim.x + threadIdx.x;
    if (idx >= nrows * kc) return;
    int r = idx / kc, j = idx % kc;
    float v = 0.f;
    if (j < k1) v = w1[(size_t)r * k1 + j];
    else if (j < k1 + k2) v = w2[(size_t)r * k2 + (j - k1)];
    wc[idx] = v;
}

__global__ void k_prep_b(const float* __restrict__ b1, const float* __restrict__ b2,
                         float* __restrict__ bc, int n) {
    int i = blockIdx.x * blockDim.x + threadIdx.x;
    if (i < n) bc[i] = b1[i] + b2[i];
}

// ---------------- z_where_bias ----------------
__global__ void k_zwb(const float* __restrict__ hid_lt, const float* __restrict__ w,
                      const float* __restrict__ b, const float* __restrict__ zwhere_lt, int t) {
    int gw = (blockIdx.x * blockDim.x + threadIdx.x) >> 5;
    int lane = threadIdx.x & 31;
    if (gw >= NB) return;
    const float* h = hid_lt + (size_t)gw * TT * HID + (size_t)t * HID;
    #pragma unroll
    for (int j = 0; j < 3; j++) {
        float s = 0.f;
        for (int k = lane; k < HID; k += 32) s += h[k] * w[j * HID + k];
        s = warp_sum(s);
        if (lane == 0) {
            g_zwb[gw * 3 + j] = fmaxf(s + b[j], 0.f) +
                                zwhere_lt[(size_t)gw * TT * 3 + (size_t)t * 3 + j];
        }
    }
}

// ---------------- glimpse bilinear sampling ----------------
__device__ __forceinline__ float samp_im(const float* __restrict__ im, int i, int y, int x) {
    if (x < 0 || x >= IMW || y < 0 || y >= IMH) return 0.f;
    return im[(size_t)i * (IMH * IMW) + y * IMW + x];
}

__global__ void k_glimpse(const float* __restrict__ im, const float* __restrict__ zw,
                          float* __restrict__ g) {
    int idx = blockIdx.x * blockDim.x + threadIdx.x;
    if (idx >= NB * 400) return;
    int i = idx / 400, p = idx % 400;
    int a = p / GG, b = p % GG;
    float s = zw[i * 3 + 0], tx = zw[i * 3 + 1], ty = zw[i * 3 + 2];
    float baseb = (2.f * b + 1.f) / (float)GG - 1.f;
    float basea = (2.f * a + 1.f) / (float)GG - 1.f;
    float x = s * baseb + tx;
    float y = s * basea + ty;
    float ix = ((x + 1.f) * (float)IMW - 1.f) * 0.5f;
    float iy = ((y + 1.f) * (float)IMH - 1.f) * 0.5f;
    float x0f = floorf(ix), y0f = floorf(iy);
    float wx = ix - x0f, wy = iy - y0f;
    int x0 = (int)x0f, y0 = (int)y0f;
    float v = samp_im(im, i, y0,     x0    ) * (1.f - wx) * (1.f - wy)
            + samp_im(im, i, y0,     x0 + 1) * wx         * (1.f - wy)
            + samp_im(im, i, y0 + 1, x0    ) * (1.f - wx) * wy
            + samp_im(im, i, y0 + 1, x0 + 1) * wx         * wy;
    g[idx] = v;
}

// ---------------- tiled fp32 GEMM: C[M,N] = A[M,K] @ W[N,K]^T + bias ----------------
// K must be a multiple of 16; M a multiple of BM. Register-prefetch double buffering.
template<int BM, int BN>
__global__ __launch_bounds__(256) void gemm_t(
    const float* __restrict__ A, const float* __restrict__ W,
    const float* __restrict__ bias, float* __restrict__ C,
    int M, int Nn, int K, int ldc, int relu)
{
    constexpr int BK = 16;
    constexpr int MT_M = BM / 16;
    constexpr int MT_N = BN / 16;
    constexpr int SA = BM + 4;
    constexpr int SW = BN + 4;
    constexpr int A_L = (BM * BK) / (256 * 4);   // float4 loads per thread
    constexpr int W_L = (BN * BK) / (256 * 4);

    __shared__ float As[BK][SA];
    __shared__ float Ws[BK][SW];

    const int tid = threadIdx.x;
    const int tx = tid & 15, ty = tid >> 4;
    const int bm = blockIdx.y * BM, bn = blockIdx.x * BN;

    int a_row[A_L], a_k4[A_L];
    const float* a_ptr[A_L];
    #pragma unroll
    for (int i = 0; i < A_L; i++) {
        int slot = tid + i * 256;
        a_row[i] = slot >> 2;
        a_k4[i]  = (slot & 3) * 4;
        a_ptr[i] = A + (size_t)(bm + a_row[i]) * K + a_k4[i];
    }
    int w_row[W_L], w_k4[W_L]; bool w_ok[W_L];
    const float* w_ptr[W_L];
    #pragma unroll
    for (int i = 0; i < W_L; i++) {
        int slot = tid + i * 256;
        w_row[i] = slot >> 2;
        w_k4[i]  = (slot & 3) * 4;
        int nn = bn + w_row[i];
        w_ok[i] = (nn < Nn);
        w_ptr[i] = W + (size_t)(w_ok[i] ? nn : 0) * K + w_k4[i];
    }

    float4 areg[A_L], wreg[W_L];
    #pragma unroll
    for (int i = 0; i < A_L; i++) areg[i] = *(const float4*)(a_ptr[i]);
    #pragma unroll
    for (int i = 0; i < W_L; i++)
        wreg[i] = w_ok[i] ? *(const float4*)(w_ptr[i]) : make_float4(0.f,0.f,0.f,0.f);

    float acc[MT_M][MT_N] = {};

    for (int k0 = 0; k0 < K; k0 += BK) {
        #pragma unroll
        for (int i = 0; i < A_L; i++) {
            As[a_k4[i]+0][a_row[i]] = areg[i].x;
            As[a_k4[i]+1][a_row[i]] = areg[i].y;
            As[a_k4[i]+2][a_row[i]] = areg[i].z;
            As[a_k4[i]+3][a_row[i]] = areg[i].w;
        }
        #pragma unroll
        for (int i = 0; i < W_L; i++) {
            Ws[w_k4[i]+0][w_row[i]] = wreg[i].x;
            Ws[w_k4[i]+1][w_row[i]] = wreg[i].y;
            Ws[w_k4[i]+2][w_row[i]] = wreg[i].z;
            Ws[w_k4[i]+3][w_row[i]] = wreg[i].w;
        }
        __syncthreads();
        if (k0 + BK < K) {
            #pragma unroll
            for (int i = 0; i < A_L; i++)
                areg[i] = *(const float4*)(a_ptr[i] + k0 + BK);
            #pragma unroll
            for (int i = 0; i < W_L; i++)
                wreg[i] = w_ok[i] ? *(const float4*)(w_ptr[i] + k0 + BK)
                                  : make_float4(0.f,0.f,0.f,0.f);
        }
        #pragma unroll
        for (int kq = 0; kq < BK; kq++) {
            float a[MT_M], b[MT_N];
            *(float4*)&a[0] = *(const float4*)&As[kq][ty * 4];
            if constexpr (MT_M == 8)
                *(float4*)&a[4] = *(const float4*)&As[kq][BM / 2 + ty * 4];
            *(float4*)&b[0] = *(const float4*)&Ws[kq][tx * 4];
            if constexpr (MT_N == 8)
                *(float4*)&b[4] = *(const float4*)&Ws[kq][BN / 2 + tx * 4];
            #pragma unroll
            for (int i = 0; i < MT_M; i++)
                #pragma unroll
                for (int j = 0; j < MT_N; j++)
                    acc[i][j] += a[i] * b[j];
        }
        __syncthreads();
    }

    #pragma unroll
    for (int i = 0; i < MT_M; i++) {
        int m = bm + ((i < 4) ? (ty * 4 + i) : (BM / 2 + ty * 4 + i - 4));
        #pragma unroll
        for (int j = 0; j < MT_N; j++) {
            int nn = bn + ((j < 4) ? (tx * 4 + j) : (BN / 2 + tx * 4 + j - 4));
            if (nn < Nn) {
                float v = acc[i][j] + (bias ? bias[nn] : 0.f);
                if (relu) v = fmaxf(v, 0.f);
                C[(size_t)m * ldc + nn] = v;
            }
        }
    }
    (void)M;
}

// ---------------- concat kernels (build combined [x | h] inputs) ----------------
__global__ void k_concat_rel(const float* __restrict__ zwhere_lt,
                             const float* __restrict__ zw_prev,
                             const float* __restrict__ zwhat_lt,
                             const float* __restrict__ zwt_prev,
                             const float* __restrict__ hid_lt, int t) {
    int idx = blockIdx.x * blockDim.x + threadIdx.x;
    if (idx >= NB * 718) return;
    int i = idx / 718, j = idx % 718;
    float v;
    if (j < 100)      v = g_enc[i * 100 + j];
    else if (j < 103) v = zwhere_lt[(size_t)i * TT * 3 + (size_t)t * 3 + (j - 100)];
    else if (j < 106) v = zw_prev[i * 3 + (j - 103)];
    else if (j < 156) v = zwhat_lt[(size_t)i * TT * 50 + (size_t)t * 50 + (j - 106)];
    else if (j < 206) v = zwt_prev[i * 50 + (j - 156)];
    else if (j < 462) v = hid_lt[(size_t)i * TT * HID + (size_t)t * HID + (j - 206)];
    else              v = g_h_rela[i * HID + (j - 462)];
    g_rel_comb[(size_t)i * KREL + j] = v;
}

__global__ void k_concat_tem(const float* __restrict__ zw_prev,
                             const float* __restrict__ hid_lt, int t) {
    int idx = blockIdx.x * blockDim.x + threadIdx.x;
    if (idx >= NB * 871) return;
    int i = idx / 871, j = idx % 871;
    float v;
    if (j < 100)      v = g_enc[i * 100 + j];
    else if (j < 103) v = zw_prev[i * 3 + (j - 100)];
    else if (j < 359) v = hid_lt[(size_t)i * TT * HID + (size_t)t * HID + (j - 103)];
    else if (j < 615) v = g_h_rela[i * HID + (j - 359)];
    else              v = g_h_rela[i * HID + (j - 615)];
    g_tem_comb[(size_t)i * KTEM + j] = v;
}

__global__ void k_concat_lwhat(const float* __restrict__ zwhat_lt,
                               const float* __restrict__ htemp_out, int t) {
    int idx = blockIdx.x * blockDim.x + threadIdx.x;
    if (idx >= NB * 562) return;
    int i = idx / 562, j = idx % 562;
    float v;
    if (j < 50)       v = zwhat_lt[(size_t)i * TT * 50 + (size_t)t * 50 + j];
    else if (j < 306) v = g_h_rela[i * HID + (j - 50)];
    else              v = htemp_out[(size_t)i * TT * HID + (size_t)t * HID + (j - 306)];
    g_lwhat_in[(size_t)i * KLW + j] = v;
}

// ---------------- LSTM elementwise ----------------
__global__ void k_lstm_rel(void) {
    int idx = blockIdx.x * blockDim.x + threadIdx.x;
    if (idx >= NB * HID) return;
    int i = idx >> 8, hh = idx & 255;
    const float* gr = g_gates + (size_t)i * 1024;
    float ig = sigmoidf_(gr[hh]);
    float fg = sigmoidf_(gr[256 + hh]);
    float gg = tanhf(gr[512 + hh]);
    float og = sigmoidf_(gr[768 + hh]);
    float c2 = fg * g_c_rela[idx] + ig * gg;
    g_c_rela[idx] = c2;
    g_h_rela[idx] = og * tanhf(c2);
}

__global__ void k_lstm_tem(float* __restrict__ htemp_out, int t) {
    int idx = blockIdx.x * blockDim.x + threadIdx.x;
    if (idx >= NB * HID) return;
    int i = idx >> 8, hh = idx & 255;
    const float* gr = g_gates + (size_t)i * 1024;
    float ig = sigmoidf_(gr[hh]);
    float fg = sigmoidf_(gr[256 + hh]);
    float gg = tanhf(gr[512 + hh]);
    float og = sigmoidf_(gr[768 + hh]);
    float c2 = fg * g_c_rela[idx] + ig * gg;
    htemp_out[(size_t)i * TT * HID + (size_t)t * HID + hh] = og * tanhf(c2);
}

// ---------------- lwhere: 6-dim projection + reparam ----------------
__global__ void k_lwhere(const float* __restrict__ w, const float* __restrict__ b,
                         const float* __restrict__ zwhere_lt, const float* __restrict__ eps_w,
                         int t, float* __restrict__ zw_cur, float* __restrict__ out_zwhere) {
    int gw = (blockIdx.x * blockDim.x + threadIdx.x) >> 5;
    int lane = threadIdx.x & 31;
    if (gw >= NB) return;
    __shared__ float mw[4][6];
    int lw = threadIdx.x >> 5;
    const float* h = g_h_rela + (size_t)gw * HID;
    const float* zl = zwhere_lt + (size_t)gw * TT * 3 + (size_t)t * 3;
    #pragma unroll
    for (int j = 0; j < 6; j++) {
        float s = 0.f;
        for (int k = lane; k < 259; k += 32) {
            float a = (k < 3) ? zl[k] : h[k - 3];
            s += a * w[j * 259 + k];
        }
        s = warp_sum(s);
        if (lane == 0) mw[lw][j] = s + b[j];
    }
    __syncwarp();
    if (lane < 3) {
        float m = mw[lw][lane];
        float sd = softplusf_(mw[lw][3 + lane]) + 1e-4f;
        float e = eps_w[(size_t)gw * TT * 3 + (size_t)t * 3 + lane];
        float z = m + sd * e;
        zw_cur[gw * 3 + lane] = z;
        out_zwhere[(size_t)gw * TT * 3 + (size_t)t * 3 + lane] = z;
        g_msw_where[gw * 6 + lane] = m;
        g_msw_where[gw * 6 + 3 + lane] = sd;
    }
}

// ---------------- what reparam ----------------
__global__ void k_what_elem(const float* __restrict__ eps_t, int t,
                            float* __restrict__ zwt_cur, float* __restrict__ out_zwhat) {
    int idx = blockIdx.x * blockDim.x + threadIdx.x;
    if (idx >= NB * WHAT) return;
    int i = idx / WHAT, j = idx % WHAT;
    float m = g_mt[i * 100 + j];
    float sd = softplusf_(g_mt[i * 100 + 50 + j]) + 1e-4f;
    float z = m + sd * eps_t[(size_t)i * TT * 50 + (size_t)t * 50 + j];
    zwt_cur[i * 50 + j] = z;
    out_zwhat[(size_t)i * TT * 50 + (size_t)t * 50 + j] = z;
    g_msw_what[i * 100 + j] = m;
    g_msw_what[i * 100 + 50 + j] = sd;
}

// ---------------- pres + KL accumulation ----------------
__global__ void k_pres_kl(const float* __restrict__ wp, const float* __restrict__ bp,
                          const float* __restrict__ zwt_cur, const float* __restrict__ zw_cur,
                          const float* __restrict__ htemp_out,
                          const float* __restrict__ u_pres, const float* __restrict__ zpres_lt,
                          int t, float* __restrict__ out_zpres,
                          float* __restrict__ out_klwhat, float* __restrict__ out_klwhere) {
    int gw = (blockIdx.x * blockDim.x + threadIdx.x) >> 5;
    int lane = threadIdx.x & 31;
    if (gw >= NB) return;
    const float* ht = htemp_out + (size_t)gw * TT * HID + (size_t)t * HID;
    const float* hr = g_h_rela + (size_t)gw * HID;
    float s = 0.f;
    for (int k = lane; k < 565; k += 32) {
        float a;
        if (k < 50)       a = zwt_cur[gw * 50 + k];
        else if (k < 53)  a = zw_cur[gw * 3 + (k - 50)];
        else if (k < 309) a = hr[k - 53];
        else              a = ht[k - 309];
        s += a * wp[k];
    }
    s = warp_sum(s);
    float p = sigmoidf_(s + bp[0]);
    float up = u_pres[(size_t)gw * TT + t];
    float zpl = zpres_lt[(size_t)gw * TT + t];
    float zp = (up < p * zpl) ? 1.f : 0.f;
    if (lane == 0) out_zpres[(size_t)gw * TT + t] = zp;

    float kw = 0.f;
    for (int j = lane; j < 50; j += 32) {
        float m = g_msw_what[gw * 100 + j];
        float sd = g_msw_what[gw * 100 + 50 + j];
        kw += -logf(sd) + (sd * sd + m * m) * 0.5f - 0.5f;
    }
    kw = warp_sum(kw);

    float kh = 0.f;
    if (lane < 3) {
        float m = g_msw_where[gw * 6 + lane];
        float sd = g_msw_where[gw * 6 + 3 + lane];
        float m0 = (lane == 0) ? 0.3f : 0.f;
        float s0 = (lane == 0) ? 0.1f : 1.f;
        kh = logf(s0 / sd) + (sd * sd + (m - m0) * (m - m0)) / (2.f * s0 * s0) - 0.5f;
    }
    kh = warp_sum(kh);

    if (lane == 0) {
        out_klwhat[gw]  += kw * zp;
        out_klwhere[gw] += kh * zp;
    }
}

// ---------------- host ----------------
static inline int cdiv(int a, int b) { return (a + b - 1) / b; }

extern "C" void kernel_launch(void* const* d_in, const int* in_sizes, int n_in,
                              void* d_out, int out_size) {
    const float* img       = (const float*)d_in[0];
    const float* zwhat_lt  = (const float*)d_in[1];
    const float* zwhere_lt = (const float*)d_in[2];
    const float* zpres_lt  = (const float*)d_in[3];
    const float* hid_lt    = (const float*)d_in[4];
    const float* eps_where = (const float*)d_in[5];
    const float* eps_what  = (const float*)d_in[6];
    const float* u_pres    = (const float*)d_in[7];
    const float* w_pro     = (const float*)d_in[8];
    const float* b_pro     = (const float*)d_in[9];
    const float* w_ge1     = (const float*)d_in[10];
    const float* b_ge1     = (const float*)d_in[11];
    const float* w_ge2     = (const float*)d_in[12];
    const float* b_ge2     = (const float*)d_in[13];
    const float* wih_rel   = (const float*)d_in[14];
    const float* whh_rel   = (const float*)d_in[15];
    const float* bih_rel   = (const float*)d_in[16];
    const float* bhh_rel   = (const float*)d_in[17];
    const float* wih_tem   = (const float*)d_in[18];
    const float* whh_tem   = (const float*)d_in[19];
    const float* bih_tem   = (const float*)d_in[20];
    const float* bhh_tem   = (const float*)d_in[21];
    const float* w_lwhere  = (const float*)d_in[22];
    const float* b_lwhere  = (const float*)d_in[23];
    const float* w_lwhat   = (const float*)d_in[24];
    const float* b_lwhat   = (const float*)d_in[25];
    const float* w_lpres   = (const float*)d_in[26];
    const float* b_lpres   = (const float*)d_in[27];

    float* out = (float*)d_out;
    float* out_zwhat   = out;                       // NB*TT*50
    float* out_zwhere  = out + 3276800;             // NB*TT*3
    float* out_zpres   = out + 3473408;             // NB*TT
    float* out_klwhat  = out + 3538944;             // NB
    float* out_klwhere = out + 3543040;             // NB
    float* out_htemp   = out + 3547136;             // NB*TT*256

    float *p_glimpse, *p_h1, *p_enc, *p_relc, *p_temc, *p_lwin, *p_gates, *p_mt;
    float *p_hrela, *p_zwb, *p_zwprev0, *p_zwtprev0;
    float *p_Wrel, *p_Wtem, *p_brel, *p_btem, *p_wge2p, *p_wlwhatp;
    cudaGetSymbolAddress((void**)&p_glimpse, g_glimpse);
    cudaGetSymbolAddress((void**)&p_h1, g_h1);
    cudaGetSymbolAddress((void**)&p_enc, g_enc);
    cudaGetSymbolAddress((void**)&p_relc, g_rel_comb);
    cudaGetSymbolAddress((void**)&p_temc, g_tem_comb);
    cudaGetSymbolAddress((void**)&p_lwin, g_lwhat_in);
    cudaGetSymbolAddress((void**)&p_gates, g_gates);
    cudaGetSymbolAddress((void**)&p_mt, g_mt);
    cudaGetSymbolAddress((void**)&p_hrela, g_h_rela);
    cudaGetSymbolAddress((void**)&p_zwb, g_zwb);
    cudaGetSymbolAddress((void**)&p_zwprev0, g_zw_prev);
    cudaGetSymbolAddress((void**)&p_zwtprev0, g_zwt_prev);
    cudaGetSymbolAddress((void**)&p_Wrel, g_Wrel);
    cudaGetSymbolAddress((void**)&p_Wtem, g_Wtem);
    cudaGetSymbolAddress((void**)&p_brel, g_brel);
    cudaGetSymbolAddress((void**)&p_btem, g_btem);
    cudaGetSymbolAddress((void**)&p_wge2p, g_wge2p);
    cudaGetSymbolAddress((void**)&p_wlwhatp, g_wlwhatp);

    float* zwbuf[2]  = { p_zwprev0,  p_zwprev0  + NB * WHERE };
    float* zwtbuf[2] = { p_zwtprev0, p_zwtprev0 + NB * WHAT  };

    // one-time prep (per graph replay; cheap)
    k_init<<<cdiv(NB * HID, 256), 256>>>(out_klwhat, out_klwhere);
    k_zero_pads<<<cdiv(NB, 256), 256>>>();
    k_prep_w<<<cdiv(1024 * KREL, 256), 256>>>(wih_rel, 462, whh_rel, 256, p_Wrel, KREL, 1024);
    k_prep_w<<<cdiv(1024 * KTEM, 256), 256>>>(wih_tem, 615, whh_tem, 256, p_Wtem, KTEM, 1024);
    k_prep_w<<<cdiv(100 * KH1, 256), 256>>>(w_ge2, 200, nullptr, 0, p_wge2p, KH1, 100);
    k_prep_w<<<cdiv(100 * KLW, 256), 256>>>(w_lwhat, 562, nullptr, 0, p_wlwhatp, KLW, 100);
    k_prep_b<<<cdiv(1024, 256), 256>>>(bih_rel, bhh_rel, p_brel, 1024);
    k_prep_b<<<cdiv(1024, 256), 256>>>(bih_tem, bhh_tem, p_btem, 1024);

    for (int t = 0; t < TT; t++) {
        int pb = t & 1;
        int cb = pb ^ 1;

        // 1) z_where_bias
        k_zwb<<<cdiv(NB * 32, 128), 128>>>(hid_lt, w_pro, b_pro, zwhere_lt, t);

        // 2) glimpse(z_where_bias) -> encoder
        k_glimpse<<<cdiv(NB * 400, 256), 256>>>(img, p_zwb, p_glimpse);
        gemm_t<64, 128><<<dim3(2, NB / 64), 256>>>(p_glimpse, w_ge1, b_ge1, p_h1,
                                                   NB, 200, 400, KH1, 1);
        gemm_t<64, 64><<<dim3(2, NB / 64), 256>>>(p_h1, p_wge2p, b_ge2, p_enc,
                                                  NB, 100, KH1, 100, 0);

        // 3) relational LSTM (single fused gate GEMM)
        k_concat_rel<<<cdiv(NB * 718, 256), 256>>>(zwhere_lt, zwbuf[pb], zwhat_lt,
                                                   zwtbuf[pb], hid_lt, t);
        gemm_t<128, 128><<<dim3(8, NB / 128), 256>>>(p_relc, p_Wrel, p_brel, p_gates,
                                                     NB, 1024, KREL, 1024, 0);
        k_lstm_rel<<<cdiv(NB * HID, 256), 256>>>();

        // 4) z_where posterior + sample
        k_lwhere<<<cdiv(NB * 32, 128), 128>>>(w_lwhere, b_lwhere, zwhere_lt, eps_where, t,
                                              zwbuf[cb], out_zwhere);

        // 5) glimpse(z_where_i) -> encoder
        k_glimpse<<<cdiv(NB * 400, 256), 256>>>(img, zwbuf[cb], p_glimpse);
        gemm_t<64, 128><<<dim3(2, NB / 64), 256>>>(p_glimpse, w_ge1, b_ge1, p_h1,
                                                   NB, 200, 400, KH1, 1);
        gemm_t<64, 64><<<dim3(2, NB / 64), 256>>>(p_h1, p_wge2p, b_ge2, p_enc,
                                                  NB, 100, KH1, 100, 0);

        // 6) temporal LSTM (single fused gate GEMM)
        k_concat_tem<<<cdiv(NB * 871, 256), 256>>>(zwbuf[pb], hid_lt, t);
        gemm_t<128, 128><<<dim3(8, NB / 128), 256>>>(p_temc, p_Wtem, p_btem, p_gates,
                                                     NB, 1024, KTEM, 1024, 0);
        k_lstm_tem<<<cdiv(NB * HID, 256), 256>>>(out_htemp, t);

        // 7) z_what posterior + sample
        k_concat_lwhat<<<cdiv(NB * 562, 256), 256>>>(zwhat_lt, out_htemp, t);
        gemm_t<64, 64><<<dim3(2, NB / 64), 256>>>(p_lwin, p_wlwhatp, b_lwhat, p_mt,
                                                  NB, 100, KLW, 100, 0);
        k_what_elem<<<cdiv(NB * WHAT, 256), 256>>>(eps_what, t, zwtbuf[cb], out_zwhat);

        // 8) presence + KL accumulation
        k_pres_kl<<<cdiv(NB * 32, 128), 128>>>(w_lpres, b_lpres, zwtbuf[cb], zwbuf[cb],
                                               out_htemp, u_pres, zpres_lt, t,
                                               out_zpres, out_klwhat, out_klwhere);
    }
    (void)in_sizes; (void)n_in; (void)out_size;
}

// round 4
// speedup vs baseline: 3.7326x; 1.1837x over previous
#include <cuda_runtime.h>
#include <cuda_bf16.h>
#include <math.h>
#include <stdint.h>

#define NB   4096
#define TT   16
#define HID  256
#define WHAT 50
#define WHERE 3
#define GG   20
#define IMH  50
#define IMW  50

// padded K sizes (multiples of 32 for tensor path)
#define KREL 736   // 718 real
#define KTEM 896   // 871 real
#define NCREL 23
#define NCTEM 28
#define KLW  576   // 562, pad 14
#define KH1  208   // 200, pad 8

// ---------------- scratch (device globals; allocation-free) ----------------
__device__ float g_h_rela[NB * HID];
__device__ float g_c_rela[NB * HID];
__device__ float g_zw_prev[2][NB * WHERE];
__device__ float g_zwt_prev[2][NB * WHAT];
__device__ float g_zwb[NB * WHERE];
__device__ float g_glimpse[NB * 400];
__device__ float g_h1[NB * KH1];
__device__ float g_enc[NB * 100];
__device__ float g_rel_hi[NB * KREL];
__device__ float g_rel_lo[NB * KREL];
__device__ float g_tem_hi[NB * KTEM];
__device__ float g_tem_lo[NB * KTEM];
__device__ float g_lwhat_in[NB * KLW];
__device__ float g_gates[NB * 1024];
__device__ float g_mt[NB * 100];
__device__ float g_msw_where[NB * 6];
__device__ float g_msw_what[NB * 100];
// combined / padded / split weights
__device__ float g_Wrel_hi[1024 * KREL];
__device__ float g_Wrel_lo[1024 * KREL];
__device__ float g_Wtem_hi[1024 * KTEM];
__device__ float g_Wtem_lo[1024 * KTEM];
__device__ float g_brel[1024];
__device__ float g_btem[1024];
__device__ float g_wge2p[100 * KH1];
__device__ float g_wlwhatp[100 * KLW];

// ---------------- helpers ----------------
__device__ __forceinline__ float sigmoidf_(float x) { return 1.f / (1.f + expf(-x)); }
__device__ __forceinline__ float softplusf_(float x) {
    return x > 0.f ? x + log1pf(expf(-x)) : log1pf(expf(x));
}
__device__ __forceinline__ float warp_sum(float v) {
    #pragma unroll
    for (int o = 16; o > 0; o >>= 1) v += __shfl_xor_sync(0xffffffffu, v, o);
    return v;
}
__device__ __forceinline__ uint32_t f32_to_tf32_bits(float x) {
    uint32_t r; asm("cvt.rna.tf32.f32 %0, %1;" : "=r"(r) : "f"(x)); return r;
}
__device__ __forceinline__ uint32_t smem_u32(const void* p) {
    uint32_t a;
    asm("{ .reg .u64 t; cvta.to.shared.u64 t, %1; cvt.u32.u64 %0, t; }" : "=r"(a) : "l"(p));
    return a;
}

#define CP_ASYNC16(dst, src) \
    asm volatile("cp.async.cg.shared.global [%0], [%1], 16;" :: "r"(dst), "l"(src))
#define CP_COMMIT() asm volatile("cp.async.commit_group;")
#define CP_WAIT1()  asm volatile("cp.async.wait_group 1;")

#define MMA_TF32(d, a, b) \
    asm volatile("mma.sync.aligned.m16n8k8.row.col.f32.tf32.tf32.f32 " \
        "{%0,%1,%2,%3}, {%4,%5,%6,%7}, {%8,%9}, {%0,%1,%2,%3};" \
        : "+f"(d[0]), "+f"(d[1]), "+f"(d[2]), "+f"(d[3]) \
        : "r"(a[0]), "r"(a[1]), "r"(a[2]), "r"(a[3]), "r"(b[0]), "r"(b[1]))

// ---------------- mma.sync 3xTF32 GEMM: C[4096,1024] = A[4096,K] @ W[1024,K]^T + bias ----
// CTA 128x128, 8 warps (2x4), warp tile 64x32, BK=32, 3-stage cp.async pipeline.
// Per stage (bytes): Ahi 16K | Alo 16K | Bhi 16K | Blo 16K = 64K; 3 stages = 192K.
#define MMA_STAGE_F 16384      // floats per stage
#define MMA_SMEM_BYTES (3 * MMA_STAGE_F * 4)

__global__ void __launch_bounds__(256, 1) gemm_mma(
    const float* __restrict__ Ahi, const float* __restrict__ Alo,
    const float* __restrict__ Bhi, const float* __restrict__ Blo,
    const float* __restrict__ bias, float* __restrict__ C, int K, int NC)
{
    extern __shared__ float smem[];
    const uint32_t sbase = smem_u32(smem);
    const int tid = threadIdx.x;
    const int wid = tid >> 5, lane = tid & 31;
    const int wm = wid >> 2, wn = wid & 3;      // 2 x 4 warp grid
    const int bm = blockIdx.y * 128, bn = blockIdx.x * 128;

    // cp.async slot geometry (per matrix: 128 rows x 8 float4)
    const int ld_row = tid >> 3;               // base row (tid covers rows 0..31)
    const int ld_k4 = tid & 7;

    // issue one stage: matrices {Ahi, Alo, Bhi, Blo}
    auto issue = [&](int c, int s) {
        const uint32_t stb = sbase + (uint32_t)s * (MMA_STAGE_F * 4);
        const float* srcs[4] = {
            Ahi + (size_t)bm * K + (size_t)c * 32,
            Alo + (size_t)bm * K + (size_t)c * 32,
            Bhi + (size_t)bn * K + (size_t)c * 32,
            Blo + (size_t)bn * K + (size_t)c * 32
        };
        #pragma unroll
        for (int mat = 0; mat < 4; mat++) {
            const float* sp = srcs[mat];
            #pragma unroll
            for (int i = 0; i < 4; i++) {
                int row = ld_row + i * 32;
                uint32_t doff = stb + (uint32_t)mat * 16384 +
                    (uint32_t)(row * 32 + ((ld_k4 ^ (row & 7)) << 2)) * 4;
                const float* gp = sp + (size_t)row * K + ld_k4 * 4;
                CP_ASYNC16(doff, gp);
            }
        }
    };

    issue(0, 0); CP_COMMIT();
    if (NC > 1) issue(1, 1);
    CP_COMMIT();

    float acc[4][4][4] = {};

    for (int c = 0; c < NC; c++) {
        const int s = c - (c / 3) * 3;
        CP_WAIT1();
        __syncthreads();
        if (c + 2 < NC) issue(c + 2, (c + 2) % 3);
        CP_COMMIT();

        const float* st = smem + s * MMA_STAGE_F;
        const float* As_h = st;
        const float* As_l = st + 4096;
        const float* Bs_h = st + 8192;
        const float* Bs_l = st + 12288;

        #pragma unroll
        for (int k8 = 0; k8 < 4; k8++) {
            const int k0 = k8 * 8;
            uint32_t ah[4][4], al[4][4], bh[4][2], bl[4][2];
            #pragma unroll
            for (int i = 0; i < 4; i++) {
                int m = wm * 64 + i * 16 + (lane >> 2);
                int sw = (m & 7) << 2;
                int o0 = m * 32 + (k0 ^ sw) + (lane & 3);
                int o4 = m * 32 + ((k0 + 4) ^ sw) + (lane & 3);
                ah[i][0] = __float_as_uint(As_h[o0]);
                ah[i][1] = __float_as_uint(As_h[o0 + 256]);   // row m+8 (same swizzle)
                ah[i][2] = __float_as_uint(As_h[o4]);
                ah[i][3] = __float_as_uint(As_h[o4 + 256]);
                al[i][0] = __float_as_uint(As_l[o0]);
                al[i][1] = __float_as_uint(As_l[o0 + 256]);
                al[i][2] = __float_as_uint(As_l[o4]);
                al[i][3] = __float_as_uint(As_l[o4 + 256]);
            }
            #pragma unroll
            for (int j = 0; j < 4; j++) {
                int n = wn * 32 + j * 8 + (lane >> 2);
                int sw = (n & 7) << 2;
                int o0 = n * 32 + (k0 ^ sw) + (lane & 3);
                int o4 = n * 32 + ((k0 + 4) ^ sw) + (lane & 3);
                bh[j][0] = __float_as_uint(Bs_h[o0]);
                bh[j][1] = __float_as_uint(Bs_h[o4]);
                bl[j][0] = __float_as_uint(Bs_l[o0]);
                bl[j][1] = __float_as_uint(Bs_l[o4]);
            }
            #pragma unroll
            for (int i = 0; i < 4; i++)
                #pragma unroll
                for (int j = 0; j < 4; j++) {
                    MMA_TF32(acc[i][j], ah[i], bh[j]);
                    MMA_TF32(acc[i][j], al[i], bh[j]);
                    MMA_TF32(acc[i][j], ah[i], bl[j]);
                }
        }
    }

    // epilogue: direct STG.64 with bias (lanes 0-3 cover 32B contiguous)
    #pragma unroll
    for (int i = 0; i < 4; i++) {
        int row = bm + wm * 64 + i * 16 + (lane >> 2);
        #pragma unroll
        for (int j = 0; j < 4; j++) {
            int col = bn + wn * 32 + j * 8 + (lane & 3) * 2;
            float b0 = bias[col], b1 = bias[col + 1];
            *(float2*)&C[(size_t)row * 1024 + col] =
                make_float2(acc[i][j][0] + b0, acc[i][j][1] + b1);
            *(float2*)&C[(size_t)(row + 8) * 1024 + col] =
                make_float2(acc[i][j][2] + b0, acc[i][j][3] + b1);
        }
    }
}

// ---------------- init ----------------
__global__ void k_init(float* kw, float* kwh) {
    int i = blockIdx.x * blockDim.x + threadIdx.x;
    if (i < NB * HID) { g_h_rela[i] = 0.f; g_c_rela[i] = 0.f; }
    if (i < NB * WHERE) g_zw_prev[0][i] = 0.f;
    if (i < NB * WHAT)  g_zwt_prev[0][i] = 0.f;
    if (i < NB) { kw[i] = 0.f; kwh[i] = 0.f; }
}

__global__ void k_zero_pads(void) {
    int i = blockIdx.x * blockDim.x + threadIdx.x;
    if (i >= NB) return;
    for (int j = 718; j < KREL; j++) { g_rel_hi[i * KREL + j] = 0.f; g_rel_lo[i * KREL + j] = 0.f; }
    for (int j = 871; j < KTEM; j++) { g_tem_hi[i * KTEM + j] = 0.f; g_tem_lo[i * KTEM + j] = 0.f; }
    for (int j = 562; j < KLW; j++)  g_lwhat_in[i * KLW + j] = 0.f;
    for (int j = 200; j < KH1; j++)  g_h1[i * KH1 + j] = 0.f;
}

// ---------------- weight prep ----------------
__global__ void k_prep_w(const float* __restrict__ w1, int k1,
                         const float* __restrict__ w2, int k2,
                         float* __restrict__ wc, int kc, int nrows) {
    int idx = blockIdx.x * blockDim.x + threadIdx.x;
    if (idx >= nrows * kc) return;
    int r = idx / kc, j = idx % kc;
    float v = 0.f;
    if (j < k1) v = w1[(size_t)r * k1 + j];
    else if (j < k1 + k2) v = w2[(size_t)r * k2 + (j - k1)];
    wc[idx] = v;
}

__global__ void k_prep_w_split(const float* __restrict__ w1, int k1,
                               const float* __restrict__ w2, int k2,
                               float* __restrict__ whi, float* __restrict__ wlo,
                               int kc, int nrows) {
    int idx = blockIdx.x * blockDim.x + threadIdx.x;
    if (idx >= nrows * kc) return;
    int r = idx / kc, j = idx % kc;
    float v = 0.f;
    if (j < k1) v = w1[(size_t)r * k1 + j];
    else if (j < k1 + k2) v = w2[(size_t)r * k2 + (j - k1)];
    float hi = __uint_as_float(f32_to_tf32_bits(v));
    whi[idx] = hi;
    wlo[idx] = v - hi;
}

__global__ void k_prep_b(const float* __restrict__ b1, const float* __restrict__ b2,
                         float* __restrict__ bc, int n) {
    int i = blockIdx.x * blockDim.x + threadIdx.x;
    if (i < n) bc[i] = b1[i] + b2[i];
}

// ---------------- z_where_bias ----------------
__global__ void k_zwb(const float* __restrict__ hid_lt, const float* __restrict__ w,
                      const float* __restrict__ b, const float* __restrict__ zwhere_lt, int t) {
    int gw = (blockIdx.x * blockDim.x + threadIdx.x) >> 5;
    int lane = threadIdx.x & 31;
    if (gw >= NB) return;
    const float* h = hid_lt + (size_t)gw * TT * HID + (size_t)t * HID;
    #pragma unroll
    for (int j = 0; j < 3; j++) {
        float s = 0.f;
        for (int k = lane; k < HID; k += 32) s += h[k] * w[j * HID + k];
        s = warp_sum(s);
        if (lane == 0) {
            g_zwb[gw * 3 + j] = fmaxf(s + b[j], 0.f) +
                                zwhere_lt[(size_t)gw * TT * 3 + (size_t)t * 3 + j];
        }
    }
}

// ---------------- glimpse bilinear sampling ----------------
__device__ __forceinline__ float samp_im(const float* __restrict__ im, int i, int y, int x) {
    if (x < 0 || x >= IMW || y < 0 || y >= IMH) return 0.f;
    return im[(size_t)i * (IMH * IMW) + y * IMW + x];
}

__global__ void k_glimpse(const float* __restrict__ im, const float* __restrict__ zw,
                          float* __restrict__ g) {
    int idx = blockIdx.x * blockDim.x + threadIdx.x;
    if (idx >= NB * 400) return;
    int i = idx / 400, p = idx % 400;
    int a = p / GG, b = p % GG;
    float s = zw[i * 3 + 0], tx = zw[i * 3 + 1], ty = zw[i * 3 + 2];
    float baseb = (2.f * b + 1.f) / (float)GG - 1.f;
    float basea = (2.f * a + 1.f) / (float)GG - 1.f;
    float x = s * baseb + tx;
    float y = s * basea + ty;
    float ix = ((x + 1.f) * (float)IMW - 1.f) * 0.5f;
    float iy = ((y + 1.f) * (float)IMH - 1.f) * 0.5f;
    float x0f = floorf(ix), y0f = floorf(iy);
    float wx = ix - x0f, wy = iy - y0f;
    int x0 = (int)x0f, y0 = (int)y0f;
    float v = samp_im(im, i, y0,     x0    ) * (1.f - wx) * (1.f - wy)
            + samp_im(im, i, y0,     x0 + 1) * wx         * (1.f - wy)
            + samp_im(im, i, y0 + 1, x0    ) * (1.f - wx) * wy
            + samp_im(im, i, y0 + 1, x0 + 1) * wx         * wy;
    g[idx] = v;
}

// ---------------- tiled fp32 GEMM (small mats): C=A@W^T+bias ----------------
template<int BM, int BN>
__global__ __launch_bounds__(256) void gemm_t(
    const float* __restrict__ A, const float* __restrict__ W,
    const float* __restrict__ bias, float* __restrict__ C,
    int M, int Nn, int K, int ldc, int relu)
{
    constexpr int BK = 16;
    constexpr int MT_M = BM / 16;
    constexpr int MT_N = BN / 16;
    constexpr int SA = BM + 4;
    constexpr int SW = BN + 4;
    constexpr int A_L = (BM * BK) / (256 * 4);
    constexpr int W_L = (BN * BK) / (256 * 4);

    __shared__ float As[BK][SA];
    __shared__ float Ws[BK][SW];

    const int tid = threadIdx.x;
    const int tx = tid & 15, ty = tid >> 4;
    const int bm = blockIdx.y * BM, bn = blockIdx.x * BN;

    int a_row[A_L], a_k4[A_L];
    const float* a_ptr[A_L];
    #pragma unroll
    for (int i = 0; i < A_L; i++) {
        int slot = tid + i * 256;
        a_row[i] = slot >> 2;
        a_k4[i]  = (slot & 3) * 4;
        a_ptr[i] = A + (size_t)(bm + a_row[i]) * K + a_k4[i];
    }
    int w_row[W_L], w_k4[W_L]; bool w_ok[W_L];
    const float* w_ptr[W_L];
    #pragma unroll
    for (int i = 0; i < W_L; i++) {
        int slot = tid + i * 256;
        w_row[i] = slot >> 2;
        w_k4[i]  = (slot & 3) * 4;
        int nn = bn + w_row[i];
        w_ok[i] = (nn < Nn);
        w_ptr[i] = W + (size_t)(w_ok[i] ? nn : 0) * K + w_k4[i];
    }

    float4 areg[A_L], wreg[W_L];
    #pragma unroll
    for (int i = 0; i < A_L; i++) areg[i] = *(const float4*)(a_ptr[i]);
    #pragma unroll
    for (int i = 0; i < W_L; i++)
        wreg[i] = w_ok[i] ? *(const float4*)(w_ptr[i]) : make_float4(0.f,0.f,0.f,0.f);

    float acc[MT_M][MT_N] = {};

    for (int k0 = 0; k0 < K; k0 += BK) {
        #pragma unroll
        for (int i = 0; i < A_L; i++) {
            As[a_k4[i]+0][a_row[i]] = areg[i].x;
            As[a_k4[i]+1][a_row[i]] = areg[i].y;
            As[a_k4[i]+2][a_row[i]] = areg[i].z;
            As[a_k4[i]+3][a_row[i]] = areg[i].w;
        }
        #pragma unroll
        for (int i = 0; i < W_L; i++) {
            Ws[w_k4[i]+0][w_row[i]] = wreg[i].x;
            Ws[w_k4[i]+1][w_row[i]] = wreg[i].y;
            Ws[w_k4[i]+2][w_row[i]] = wreg[i].z;
            Ws[w_k4[i]+3][w_row[i]] = wreg[i].w;
        }
        __syncthreads();
        if (k0 + BK < K) {
            #pragma unroll
            for (int i = 0; i < A_L; i++)
                areg[i] = *(const float4*)(a_ptr[i] + k0 + BK);
            #pragma unroll
            for (int i = 0; i < W_L; i++)
                wreg[i] = w_ok[i] ? *(const float4*)(w_ptr[i] + k0 + BK)
                                  : make_float4(0.f,0.f,0.f,0.f);
        }
        #pragma unroll
        for (int kq = 0; kq < BK; kq++) {
            float a[MT_M], b[MT_N];
            *(float4*)&a[0] = *(const float4*)&As[kq][ty * 4];
            if constexpr (MT_M == 8)
                *(float4*)&a[4] = *(const float4*)&As[kq][BM / 2 + ty * 4];
            *(float4*)&b[0] = *(const float4*)&Ws[kq][tx * 4];
            if constexpr (MT_N == 8)
                *(float4*)&b[4] = *(const float4*)&Ws[kq][BN / 2 + tx * 4];
            #pragma unroll
            for (int i = 0; i < MT_M; i++)
                #pragma unroll
                for (int j = 0; j < MT_N; j++)
                    acc[i][j] += a[i] * b[j];
        }
        __syncthreads();
    }

    #pragma unroll
    for (int i = 0; i < MT_M; i++) {
        int m = bm + ((i < 4) ? (ty * 4 + i) : (BM / 2 + ty * 4 + i - 4));
        #pragma unroll
        for (int j = 0; j < MT_N; j++) {
            int nn = bn + ((j < 4) ? (tx * 4 + j) : (BN / 2 + tx * 4 + j - 4));
            if (nn < Nn) {
                float v = acc[i][j] + (bias ? bias[nn] : 0.f);
                if (relu) v = fmaxf(v, 0.f);
                C[(size_t)m * ldc + nn] = v;
            }
        }
    }
    (void)M;
}

// ---------------- concat + tf32 split kernels ----------------
__global__ void k_concat_rel(const float* __restrict__ zwhere_lt,
                             const float* __restrict__ zw_prev,
                             const float* __restrict__ zwhat_lt,
                             const float* __restrict__ zwt_prev,
                             const float* __restrict__ hid_lt, int t) {
    int idx = blockIdx.x * blockDim.x + threadIdx.x;
    if (idx >= NB * 718) return;
    int i = idx / 718, j = idx % 718;
    float v;
    if (j < 100)      v = g_enc[i * 100 + j];
    else if (j < 103) v = zwhere_lt[(size_t)i * TT * 3 + (size_t)t * 3 + (j - 100)];
    else if (j < 106) v = zw_prev[i * 3 + (j - 103)];
    else if (j < 156) v = zwhat_lt[(size_t)i * TT * 50 + (size_t)t * 50 + (j - 106)];
    else if (j < 206) v = zwt_prev[i * 50 + (j - 156)];
    else if (j < 462) v = hid_lt[(size_t)i * TT * HID + (size_t)t * HID + (j - 206)];
    else              v = g_h_rela[i * HID + (j - 462)];
    float hi = __uint_as_float(f32_to_tf32_bits(v));
    g_rel_hi[(size_t)i * KREL + j] = hi;
    g_rel_lo[(size_t)i * KREL + j] = v - hi;
}

__global__ void k_concat_tem(const float* __restrict__ zw_prev,
                             const float* __restrict__ hid_lt, int t) {
    int idx = blockIdx.x * blockDim.x + threadIdx.x;
    if (idx >= NB * 871) return;
    int i = idx / 871, j = idx % 871;
    float v;
    if (j < 100)      v = g_enc[i * 100 + j];
    else if (j < 103) v = zw_prev[i * 3 + (j - 100)];
    else if (j < 359) v = hid_lt[(size_t)i * TT * HID + (size_t)t * HID + (j - 103)];
    else if (j < 615) v = g_h_rela[i * HID + (j - 359)];
    else              v = g_h_rela[i * HID + (j - 615)];
    float hi = __uint_as_float(f32_to_tf32_bits(v));
    g_tem_hi[(size_t)i * KTEM + j] = hi;
    g_tem_lo[(size_t)i * KTEM + j] = v - hi;
}

__global__ void k_concat_lwhat(const float* __restrict__ zwhat_lt,
                               const float* __restrict__ htemp_out, int t) {
    int idx = blockIdx.x * blockDim.x + threadIdx.x;
    if (idx >= NB * 562) return;
    int i = idx / 562, j = idx % 562;
    float v;
    if (j < 50)       v = zwhat_lt[(size_t)i * TT * 50 + (size_t)t * 50 + j];
    else if (j < 306) v = g_h_rela[i * HID + (j - 50)];
    else              v = htemp_out[(size_t)i * TT * HID + (size_t)t * HID + (j - 306)];
    g_lwhat_in[(size_t)i * KLW + j] = v;
}

// ---------------- LSTM elementwise ----------------
__global__ void k_lstm_rel(void) {
    int idx = blockIdx.x * blockDim.x + threadIdx.x;
    if (idx >= NB * HID) return;
    int i = idx >> 8, hh = idx & 255;
    const float* gr = g_gates + (size_t)i * 1024;
    float ig = sigmoidf_(gr[hh]);
    float fg = sigmoidf_(gr[256 + hh]);
    float gg = tanhf(gr[512 + hh]);
    float og = sigmoidf_(gr[768 + hh]);
    float c2 = fg * g_c_rela[idx] + ig * gg;
    g_c_rela[idx] = c2;
    g_h_rela[idx] = og * tanhf(c2);
}

__global__ void k_lstm_tem(float* __restrict__ htemp_out, int t) {
    int idx = blockIdx.x * blockDim.x + threadIdx.x;
    if (idx >= NB * HID) return;
    int i = idx >> 8, hh = idx & 255;
    const float* gr = g_gates + (size_t)i * 1024;
    float ig = sigmoidf_(gr[hh]);
    float fg = sigmoidf_(gr[256 + hh]);
    float gg = tanhf(gr[512 + hh]);
    float og = sigmoidf_(gr[768 + hh]);
    float c2 = fg * g_c_rela[idx] + ig * gg;
    htemp_out[(size_t)i * TT * HID + (size_t)t * HID + hh] = og * tanhf(c2);
}

// ---------------- lwhere: 6-dim projection + reparam ----------------
__global__ void k_lwhere(const float* __restrict__ w, const float* __restrict__ b,
                         const float* __restrict__ zwhere_lt, const float* __restrict__ eps_w,
                         int t, float* __restrict__ zw_cur, float* __restrict__ out_zwhere) {
    int gw = (blockIdx.x * blockDim.x + threadIdx.x) >> 5;
    int lane = threadIdx.x & 31;
    if (gw >= NB) return;
    __shared__ float mw[4][6];
    int lw = threadIdx.x >> 5;
    const float* h = g_h_rela + (size_t)gw * HID;
    const float* zl = zwhere_lt + (size_t)gw * TT * 3 + (size_t)t * 3;
    #pragma unroll
    for (int j = 0; j < 6; j++) {
        float s = 0.f;
        for (int k = lane; k < 259; k += 32) {
            float a = (k < 3) ? zl[k] : h[k - 3];
            s += a * w[j * 259 + k];
        }
        s = warp_sum(s);
        if (lane == 0) mw[lw][j] = s + b[j];
    }
    __syncwarp();
    if (lane < 3) {
        float m = mw[lw][lane];
        float sd = softplusf_(mw[lw][3 + lane]) + 1e-4f;
        float e = eps_w[(size_t)gw * TT * 3 + (size_t)t * 3 + lane];
        float z = m + sd * e;
        zw_cur[gw * 3 + lane] = z;
        out_zwhere[(size_t)gw * TT * 3 + (size_t)t * 3 + lane] = z;
        g_msw_where[gw * 6 + lane] = m;
        g_msw_where[gw * 6 + 3 + lane] = sd;
    }
}

// ---------------- what reparam ----------------
__global__ void k_what_elem(const float* __restrict__ eps_t, int t,
                            float* __restrict__ zwt_cur, float* __restrict__ out_zwhat) {
    int idx = blockIdx.x * blockDim.x + threadIdx.x;
    if (idx >= NB * WHAT) return;
    int i = idx / WHAT, j = idx % WHAT;
    float m = g_mt[i * 100 + j];
    float sd = softplusf_(g_mt[i * 100 + 50 + j]) + 1e-4f;
    float z = m + sd * eps_t[(size_t)i * TT * 50 + (size_t)t * 50 + j];
    zwt_cur[i * 50 + j] = z;
    out_zwhat[(size_t)i * TT * 50 + (size_t)t * 50 + j] = z;
    g_msw_what[i * 100 + j] = m;
    g_msw_what[i * 100 + 50 + j] = sd;
}

// ---------------- pres + KL accumulation ----------------
__global__ void k_pres_kl(const float* __restrict__ wp, const float* __restrict__ bp,
                          const float* __restrict__ zwt_cur, const float* __restrict__ zw_cur,
                          const float* __restrict__ htemp_out,
                          const float* __restrict__ u_pres, const float* __restrict__ zpres_lt,
                          int t, float* __restrict__ out_zpres,
                          float* __restrict__ out_klwhat, float* __restrict__ out_klwhere) {
    int gw = (blockIdx.x * blockDim.x + threadIdx.x) >> 5;
    int lane = threadIdx.x & 31;
    if (gw >= NB) return;
    const float* ht = htemp_out + (size_t)gw * TT * HID + (size_t)t * HID;
    const float* hr = g_h_rela + (size_t)gw * HID;
    float s = 0.f;
    for (int k = lane; k < 565; k += 32) {
        float a;
        if (k < 50)       a = zwt_cur[gw * 50 + k];
        else if (k < 53)  a = zw_cur[gw * 3 + (k - 50)];
        else if (k < 309) a = hr[k - 53];
        else              a = ht[k - 309];
        s += a * wp[k];
    }
    s = warp_sum(s);
    float p = sigmoidf_(s + bp[0]);
    float up = u_pres[(size_t)gw * TT + t];
    float zpl = zpres_lt[(size_t)gw * TT + t];
    float zp = (up < p * zpl) ? 1.f : 0.f;
    if (lane == 0) out_zpres[(size_t)gw * TT + t] = zp;

    float kw = 0.f;
    for (int j = lane; j < 50; j += 32) {
        float m = g_msw_what[gw * 100 + j];
        float sd = g_msw_what[gw * 100 + 50 + j];
        kw += -logf(sd) + (sd * sd + m * m) * 0.5f - 0.5f;
    }
    kw = warp_sum(kw);

    float kh = 0.f;
    if (lane < 3) {
        float m = g_msw_where[gw * 6 + lane];
        float sd = g_msw_where[gw * 6 + 3 + lane];
        float m0 = (lane == 0) ? 0.3f : 0.f;
        float s0 = (lane == 0) ? 0.1f : 1.f;
        kh = logf(s0 / sd) + (sd * sd + (m - m0) * (m - m0)) / (2.f * s0 * s0) - 0.5f;
    }
    kh = warp_sum(kh);

    if (lane == 0) {
        out_klwhat[gw]  += kw * zp;
        out_klwhere[gw] += kh * zp;
    }
}

// ---------------- host ----------------
static inline int cdiv(int a, int b) { return (a + b - 1) / b; }

extern "C" void kernel_launch(void* const* d_in, const int* in_sizes, int n_in,
                              void* d_out, int out_size) {
    const float* img       = (const float*)d_in[0];
    const float* zwhat_lt  = (const float*)d_in[1];
    const float* zwhere_lt = (const float*)d_in[2];
    const float* zpres_lt  = (const float*)d_in[3];
    const float* hid_lt    = (const float*)d_in[4];
    const float* eps_where = (const float*)d_in[5];
    const float* eps_what  = (const float*)d_in[6];
    const float* u_pres    = (const float*)d_in[7];
    const float* w_pro     = (const float*)d_in[8];
    const float* b_pro     = (const float*)d_in[9];
    const float* w_ge1     = (const float*)d_in[10];
    const float* b_ge1     = (const float*)d_in[11];
    const float* w_ge2     = (const float*)d_in[12];
    const float* b_ge2     = (const float*)d_in[13];
    const float* wih_rel   = (const float*)d_in[14];
    const float* whh_rel   = (const float*)d_in[15];
    const float* bih_rel   = (const float*)d_in[16];
    const float* bhh_rel   = (const float*)d_in[17];
    const float* wih_tem   = (const float*)d_in[18];
    const float* whh_tem   = (const float*)d_in[19];
    const float* bih_tem   = (const float*)d_in[20];
    const float* bhh_tem   = (const float*)d_in[21];
    const float* w_lwhere  = (const float*)d_in[22];
    const float* b_lwhere  = (const float*)d_in[23];
    const float* w_lwhat   = (const float*)d_in[24];
    const float* b_lwhat   = (const float*)d_in[25];
    const float* w_lpres   = (const float*)d_in[26];
    const float* b_lpres   = (const float*)d_in[27];

    float* out = (float*)d_out;
    float* out_zwhat   = out;
    float* out_zwhere  = out + 3276800;
    float* out_zpres   = out + 3473408;
    float* out_klwhat  = out + 3538944;
    float* out_klwhere = out + 3543040;
    float* out_htemp   = out + 3547136;

    cudaFuncSetAttribute(gemm_mma, cudaFuncAttributeMaxDynamicSharedMemorySize, MMA_SMEM_BYTES);

    float *p_glimpse, *p_h1, *p_enc, *p_lwin, *p_gates, *p_mt;
    float *p_hrela, *p_zwb, *p_zwprev0, *p_zwtprev0;
    float *p_relhi, *p_rello, *p_temhi, *p_temlo;
    float *p_Wrelhi, *p_Wrello, *p_Wtemhi, *p_Wtemlo;
    float *p_brel, *p_btem, *p_wge2p, *p_wlwhatp;
    cudaGetSymbolAddress((void**)&p_glimpse, g_glimpse);
    cudaGetSymbolAddress((void**)&p_h1, g_h1);
    cudaGetSymbolAddress((void**)&p_enc, g_enc);
    cudaGetSymbolAddress((void**)&p_lwin, g_lwhat_in);
    cudaGetSymbolAddress((void**)&p_gates, g_gates);
    cudaGetSymbolAddress((void**)&p_mt, g_mt);
    cudaGetSymbolAddress((void**)&p_hrela, g_h_rela);
    cudaGetSymbolAddress((void**)&p_zwb, g_zwb);
    cudaGetSymbolAddress((void**)&p_zwprev0, g_zw_prev);
    cudaGetSymbolAddress((void**)&p_zwtprev0, g_zwt_prev);
    cudaGetSymbolAddress((void**)&p_relhi, g_rel_hi);
    cudaGetSymbolAddress((void**)&p_rello, g_rel_lo);
    cudaGetSymbolAddress((void**)&p_temhi, g_tem_hi);
    cudaGetSymbolAddress((void**)&p_temlo, g_tem_lo);
    cudaGetSymbolAddress((void**)&p_Wrelhi, g_Wrel_hi);
    cudaGetSymbolAddress((void**)&p_Wrello, g_Wrel_lo);
    cudaGetSymbolAddress((void**)&p_Wtemhi, g_Wtem_hi);
    cudaGetSymbolAddress((void**)&p_Wtemlo, g_Wtem_lo);
    cudaGetSymbolAddress((void**)&p_brel, g_brel);
    cudaGetSymbolAddress((void**)&p_btem, g_btem);
    cudaGetSymbolAddress((void**)&p_wge2p, g_wge2p);
    cudaGetSymbolAddress((void**)&p_wlwhatp, g_wlwhatp);

    float* zwbuf[2]  = { p_zwprev0,  p_zwprev0  + NB * WHERE };
    float* zwtbuf[2] = { p_zwtprev0, p_zwtprev0 + NB * WHAT  };

    // one-time prep (per replay; cheap)
    k_init<<<cdiv(NB * HID, 256), 256>>>(out_klwhat, out_klwhere);
    k_zero_pads<<<cdiv(NB, 256), 256>>>();
    k_prep_w_split<<<cdiv(1024 * KREL, 256), 256>>>(wih_rel, 462, whh_rel, 256,
                                                    p_Wrelhi, p_Wrello, KREL, 1024);
    k_prep_w_split<<<cdiv(1024 * KTEM, 256), 256>>>(wih_tem, 615, whh_tem, 256,
                                                    p_Wtemhi, p_Wtemlo, KTEM, 1024);
    k_prep_w<<<cdiv(100 * KH1, 256), 256>>>(w_ge2, 200, nullptr, 0, p_wge2p, KH1, 100);
    k_prep_w<<<cdiv(100 * KLW, 256), 256>>>(w_lwhat, 562, nullptr, 0, p_wlwhatp, KLW, 100);
    k_prep_b<<<cdiv(1024, 256), 256>>>(bih_rel, bhh_rel, p_brel, 1024);
    k_prep_b<<<cdiv(1024, 256), 256>>>(bih_tem, bhh_tem, p_btem, 1024);

    for (int t = 0; t < TT; t++) {
        int pb = t & 1;
        int cb = pb ^ 1;

        // 1) z_where_bias
        k_zwb<<<cdiv(NB * 32, 128), 128>>>(hid_lt, w_pro, b_pro, zwhere_lt, t);

        // 2) glimpse(z_where_bias) -> encoder
        k_glimpse<<<cdiv(NB * 400, 256), 256>>>(img, p_zwb, p_glimpse);
        gemm_t<64, 128><<<dim3(2, NB / 64), 256>>>(p_glimpse, w_ge1, b_ge1, p_h1,
                                                   NB, 200, 400, KH1, 1);
        gemm_t<64, 64><<<dim3(2, NB / 64), 256>>>(p_h1, p_wge2p, b_ge2, p_enc,
                                                  NB, 100, KH1, 100, 0);

        // 3) relational LSTM — mma.sync 3xTF32 fused gate GEMM
        k_concat_rel<<<cdiv(NB * 718, 256), 256>>>(zwhere_lt, zwbuf[pb], zwhat_lt,
                                                   zwtbuf[pb], hid_lt, t);
        gemm_mma<<<dim3(8, 32), 256, MMA_SMEM_BYTES>>>(p_relhi, p_rello, p_Wrelhi, p_Wrello,
                                                       p_brel, p_gates, KREL, NCREL);
        k_lstm_rel<<<cdiv(NB * HID, 256), 256>>>();

        // 4) z_where posterior + sample
        k_lwhere<<<cdiv(NB * 32, 128), 128>>>(w_lwhere, b_lwhere, zwhere_lt, eps_where, t,
                                              zwbuf[cb], out_zwhere);

        // 5) glimpse(z_where_i) -> encoder
        k_glimpse<<<cdiv(NB * 400, 256), 256>>>(img, zwbuf[cb], p_glimpse);
        gemm_t<64, 128><<<dim3(2, NB / 64), 256>>>(p_glimpse, w_ge1, b_ge1, p_h1,
                                                   NB, 200, 400, KH1, 1);
        gemm_t<64, 64><<<dim3(2, NB / 64), 256>>>(p_h1, p_wge2p, b_ge2, p_enc,
                                                  NB, 100, KH1, 100, 0);

        // 6) temporal LSTM — mma.sync 3xTF32 fused gate GEMM
        k_concat_tem<<<cdiv(NB * 871, 256), 256>>>(zwbuf[pb], hid_lt, t);
        gemm_mma<<<dim3(8, 32), 256, MMA_SMEM_BYTES>>>(p_temhi, p_temlo, p_Wtemhi, p_Wtemlo,
                                                       p_btem, p_gates, KTEM, NCTEM);
        k_lstm_tem<<<cdiv(NB * HID, 256), 256>>>(out_htemp, t);

        // 7) z_what posterior + sample
        k_concat_lwhat<<<cdiv(NB * 562, 256), 256>>>(zwhat_lt, out_htemp, t);
        gemm_t<64, 64><<<dim3(2, NB / 64), 256>>>(p_lwin, p_wlwhatp, b_lwhat, p_mt,
                                                  NB, 100, KLW, 100, 0);
        k_what_elem<<<cdiv(NB * WHAT, 256), 256>>>(eps_what, t, zwtbuf[cb], out_zwhat);

        // 8) presence + KL accumulation
        k_pres_kl<<<cdiv(NB * 32, 128), 128>>>(w_lpres, b_lpres, zwtbuf[cb], zwbuf[cb],
                                               out_htemp, u_pres, zpres_lt, t,
                                               out_zpres, out_klwhat, out_klwhere);
    }
    (void)in_sizes; (void)n_in; (void)out_size;
}